// round 16
// baseline (speedup 1.0000x reference)
#include <cuda_runtime.h>
#include <cuda_bf16.h>
#include <math.h>
#include <stdint.h>

#define TT   512
#define BB   64
#define EE   256
#define UU   512
#define G4U  2048
#define NCTA 128   // 64 per direction
#define NTHR 256
#define ZS2  66    // k_rec z stride (floats, even)

// -------- device scratch --------
__device__ __align__(16) float g_Y[(size_t)2 * TT * G4U * BB];   // [dir][t][n][b]
// h in MMA-fragment order: [parity][dir][kc(32)][mtile(8)][lane(32)][16B = a0 a1 a2 a3]
// a0 = rows(lane>>2) cols(lane&3)*2+{0,1}; a1 = rows+8; a2 = cols+8; a3 = rows+8,cols+8
// (rows = m within 16-tile, m = split*64 + b; cols = k within 16-chunk, k = u)
__device__ __align__(128) char g_hF[2][2][131072];
__device__ __align__(16) float g_hfin[2][UU * BB];               // final h fp32 [dir][u*64+b]
__device__ __align__(16) __nv_bfloat16 g_X[TT][2][BB][EE];       // [t][split][b][e]
__device__ __align__(16) __nv_bfloat16 g_Wxb[2][G4U][EE];        // [dir][n][e]  (hi only)
__device__ unsigned g_flag[2][64][16];                           // 64B-spaced step flags
__device__ unsigned g_cnt[2][32];
__device__ unsigned g_gen[2][32];

// fast transcendentals (ex2.approx-based; saturate correctly at +-inf)
__device__ __forceinline__ float fsigm(float x) {
    return __fdividef(1.0f, 1.0f + __expf(-x));
}
__device__ __forceinline__ float ftanh(float x) {
    return __fdividef(2.0f, 1.0f + __expf(-2.0f * x)) - 1.0f;
}

__device__ __forceinline__ uint32_t smem_u32(const void* p) {
    uint32_t a;
    asm("{ .reg .u64 t; cvta.to.shared.u64 t, %1; cvt.u32.u64 %0, t; }" : "=r"(a) : "l"(p));
    return a;
}
__device__ __forceinline__ void ldm4(uint32_t* r, uint32_t addr) {
    asm volatile("ldmatrix.sync.aligned.m8n8.x4.shared.b16 {%0,%1,%2,%3}, [%4];"
                 : "=r"(r[0]), "=r"(r[1]), "=r"(r[2]), "=r"(r[3]) : "r"(addr));
}
__device__ __forceinline__ void mma16816(float* d, const uint32_t* a, uint32_t b0, uint32_t b1) {
    asm volatile("mma.sync.aligned.m16n8k16.row.col.f32.bf16.bf16.f32 "
                 "{%0,%1,%2,%3}, {%4,%5,%6,%7}, {%8,%9}, {%0,%1,%2,%3};"
                 : "+f"(d[0]), "+f"(d[1]), "+f"(d[2]), "+f"(d[3])
                 : "r"(a[0]), "r"(a[1]), "r"(a[2]), "r"(a[3]), "r"(b0), "r"(b1));
}

// -------- prep: Wx -> bf16 hi, n-major --------
__global__ __launch_bounds__(256) void k_prepw(const float* __restrict__ Wxf,
                                               const float* __restrict__ Wxb)
{
    int bid = blockIdx.x;
    int dir = bid >> 11, n = bid & 2047;
    const float* Wx = dir ? Wxb : Wxf;
    int e = threadIdx.x;
    float w = Wx[(size_t)e * G4U + n];
    g_Wxb[dir][n][e] = __float2bfloat16(w);
}

// -------- prep: embedding gather -> bf16 hi/lo --------
__global__ __launch_bounds__(256) void k_prepx(const int* __restrict__ sent,
                                               const float* __restrict__ emb)
{
    int t = blockIdx.x;
    int b0 = blockIdx.y * 16;
    int tid = threadIdx.x;
    __shared__ int vrow[16];
    if (tid < 16) vrow[tid] = sent[(b0 + tid) * TT + t];
    __syncthreads();
    for (int j = 0; j < 16; j++) {
        int b = b0 + j;
        float v = emb[(size_t)vrow[j] * EE + tid];
        __nv_bfloat16 hi = __float2bfloat16(v);
        __nv_bfloat16 lo = __float2bfloat16(v - __bfloat162float(hi));
        g_X[t][0][b][tid] = hi;
        g_X[t][1][b][tid] = lo;
    }
}

// -------- input projection via HMMA (R14, unchanged) --------
__global__ __launch_bounds__(256) void k_xw2(const float* __restrict__ bf,
                                             const float* __restrict__ bbv)
{
    int bid = blockIdx.x;
    int t = bid >> 5;
    int r5 = bid & 31;
    int dir = r5 >> 4, ntile = r5 & 15;

    extern __shared__ char sm[];
    char* smA = sm;
    char* smB = sm + 65536;
    float* zst = (float*)sm;

    int tid = threadIdx.x, lane = tid & 31, w = tid >> 5;

    {
        const uint4* Xs = (const uint4*)&g_X[t][0][0][0];
        #pragma unroll
        for (int idx = tid; idx < 4096; idx += 256) {
            int row = idx >> 5, c = idx & 31;
            uint4 v = __ldcg(Xs + idx);
            *(uint4*)(smA + row * 512 + ((c ^ (row & 7)) << 4)) = v;
        }
    }
    {
        const uint4* Ws = (const uint4*)&g_Wxb[dir][0][0];
        #pragma unroll
        for (int idx = tid; idx < 4096; idx += 256) {
            int q = idx >> 5, c = idx & 31;
            uint4 v = __ldcg(Ws + ((size_t)(ntile * 128 + q)) * 32 + c);
            *(uint4*)(smB + q * 512 + ((c ^ (q & 7)) << 4)) = v;
        }
    }
    __syncthreads();

    uint32_t smA32 = smem_u32(smA), smB32 = smem_u32(smB);
    int arows = (w & 3) * 32;
    int brows = (w >> 2) * 64;

    float D[2][8][4];
    {
        uint32_t aBase[2]; int ar7[2];
        uint32_t bBase[4]; int br7[4];
        int dA = (lane >> 4) & 1, dB = (lane >> 3) & 1;
        #pragma unroll
        for (int mi = 0; mi < 2; mi++) {
            int row = arows + mi * 16 + ((lane >> 3) & 1) * 8 + (lane & 7);
            aBase[mi] = smA32 + row * 512;
            ar7[mi] = row & 7;
        }
        #pragma unroll
        for (int nt = 0; nt < 4; nt++) {
            int row = brows + nt * 16 + ((lane >> 4) & 1) * 8 + (lane & 7);
            bBase[nt] = smB32 + row * 512;
            br7[nt] = row & 7;
        }
        #pragma unroll
        for (int mi = 0; mi < 2; mi++)
            #pragma unroll
            for (int nj = 0; nj < 8; nj++)
                #pragma unroll
                for (int e = 0; e < 4; e++) D[mi][nj][e] = 0.0f;

        #pragma unroll 2
        for (int j = 0; j < 16; j++) {
            uint32_t af[2][4], bb[4][4];
            #pragma unroll
            for (int mi = 0; mi < 2; mi++)
                ldm4(af[mi], aBase[mi] + ((((2 * j + dA) ^ ar7[mi])) << 4));
            #pragma unroll
            for (int nt = 0; nt < 4; nt++)
                ldm4(bb[nt], bBase[nt] + ((((2 * j + dB) ^ br7[nt])) << 4));
            #pragma unroll
            for (int mi = 0; mi < 2; mi++)
                #pragma unroll
                for (int nt = 0; nt < 4; nt++) {
                    mma16816(D[mi][2 * nt + 0], af[mi], bb[nt][0], bb[nt][1]);
                    mma16816(D[mi][2 * nt + 1], af[mi], bb[nt][2], bb[nt][3]);
                }
        }
    }
    __syncthreads();

    {
        int g = lane >> 2, tq = lane & 3;
        #pragma unroll
        for (int mi = 0; mi < 2; mi++)
            #pragma unroll
            for (int nj = 0; nj < 8; nj++) {
                int r = arows + mi * 16 + g;
                int c = brows + nj * 8 + 2 * tq;
                zst[r * 129 + c]           = D[mi][nj][0];
                zst[r * 129 + c + 1]       = D[mi][nj][1];
                zst[(r + 8) * 129 + c]     = D[mi][nj][2];
                zst[(r + 8) * 129 + c + 1] = D[mi][nj][3];
            }
    }
    __syncthreads();

    {
        const float* bias = dir ? bbv : bf;
        float* Y = g_Y + ((size_t)dir * TT + t) * (size_t)(G4U * BB)
                       + (size_t)ntile * 128 * BB;
        #pragma unroll
        for (int rep = 0; rep < 8; rep++) {
            int task = tid + 256 * rep;
            int n = task >> 4, b4 = (task & 15) << 2;
            float bn = bias[ntile * 128 + n];
            float4 o;
            o.x = zst[(b4 + 0) * 129 + n] + zst[(b4 + 64) * 129 + n] + bn;
            o.y = zst[(b4 + 1) * 129 + n] + zst[(b4 + 65) * 129 + n] + bn;
            o.z = zst[(b4 + 2) * 129 + n] + zst[(b4 + 66) * 129 + n] + bn;
            o.w = zst[(b4 + 3) * 129 + n] + zst[(b4 + 67) * 129 + n] + bn;
            *(float4*)(Y + (size_t)n * BB + b4) = o;
        }
    }
}

// -------- persistent HMMA recurrence: A direct from gmem fragments --------
// warp w: m-block mb = w&3 (mtiles 2mb,2mb+1), K-half kh = w>>2 (kc = kh*16..+16)
__global__ __launch_bounds__(NTHR, 1) void k_rec(
    const float* __restrict__ Whf, const float* __restrict__ Whb)
{
    extern __shared__ char dsm[];
    char* smB  = dsm;                              // 32768 B (W_hi)
    float* zst = (float*)(dsm + 32768);            // [128][ZS2] = 33792 B
    __nv_bfloat16* hstage = (__nv_bfloat16*)(dsm + 32768 + 33792); // 2048 B

    int tid = threadIdx.x, lane = tid & 31, w = tid >> 5;
    int dir = blockIdx.x >> 6;
    int cta = blockIdx.x & 63;
    int u0  = cta * 8;
    const float* Wh = dir ? Whb : Whf;

    // B build (once): 32 rows of W_hi (k-major, 1024B rows, XOR swizzle)
    for (int idx = tid; idx < 32 * 512; idx += NTHR) {
        int n = idx >> 9, k = idx & 511;
        float wv = Wh[(size_t)k * G4U + ((n >> 3) * UU + u0 + (n & 7))];
        __nv_bfloat16 hi = __float2bfloat16(wv);
        uint32_t off = (uint32_t)(n * 1024 + ((((k >> 3) ^ (n & 7))) << 4) + (k & 7) * 2);
        *(__nv_bfloat16*)(smB + off) = hi;
    }
    for (int i = tid; i < 128 * ZS2; i += NTHR) zst[i] = 0.0f;

    uint32_t smB32 = smem_u32(smB);
    int mb   = w & 3;
    int kh   = w >> 2;
    int arow = mb * 32;          // zst row base
    int zcol = kh * 32;

    uint32_t bBase[2], bSw[2][4];
    {
        int dB = (lane >> 3) & 1;
        #pragma unroll
        for (int nt = 0; nt < 2; nt++) {
            int row = nt * 16 + ((lane >> 4) & 1) * 8 + (lane & 7);
            bBase[nt] = smB32 + row * 1024;
            #pragma unroll
            for (int j = 0; j < 4; j++)
                bSw[nt][j] = (uint32_t)(((2 * j + dB) ^ (row & 7)) << 4);
        }
    }

    int b = tid & 63, du0 = tid >> 6;
    float creg[2] = {0.0f, 0.0f};
    const float* Ybase = g_Y + (size_t)dir * TT * (size_t)(G4U * BB);
    __syncthreads();

    for (int t = 0; t < TT; t++) {
        int ttv = dir ? (TT - 1 - t) : t;
        const float* Yt = Ybase + (size_t)ttv * (size_t)(G4U * BB);
        float yv[8];
        #pragma unroll
        for (int g = 0; g < 4; g++) {
            yv[g]     = __ldcg(Yt + (size_t)(g * UU + u0 + du0) * BB + b);
            yv[4 + g] = __ldcg(Yt + (size_t)(g * UU + u0 + du0 + 4) * BB + b);
        }

        if (t > 0) {
            // barrier wait for producers of h(t)
            if (tid < 64) {
                while (*(volatile unsigned*)&g_flag[dir][tid][0] < (unsigned)t) {}
            }
            __syncthreads();

            const uint4* Af = (const uint4*)&g_hF[t & 1][dir][0];

            float D[2][4][4];
            #pragma unroll
            for (int mt = 0; mt < 2; mt++)
                #pragma unroll
                for (int nj = 0; nj < 4; nj++)
                    #pragma unroll
                    for (int e = 0; e < 4; e++) D[mt][nj][e] = 0.0f;

            // 4 groups of 4 kc: prefetch 8 LDG.128, then 4 MMA iters
            for (int grp = 0; grp < 4; grp++) {
                int kc0 = kh * 16 + grp * 4;
                uint4 af[2][4];
                #pragma unroll
                for (int mt = 0; mt < 2; mt++)
                    #pragma unroll
                    for (int kk = 0; kk < 4; kk++)
                        af[mt][kk] = __ldcg(Af + ((size_t)(kc0 + kk) * 8 + (2 * mb + mt)) * 32 + lane);
                #pragma unroll
                for (int kk = 0; kk < 4; kk++) {
                    int kc = kc0 + kk;
                    uint32_t qb = (uint32_t)((kc >> 2) * 128);
                    int jb = kc & 3;
                    uint32_t p0[4], p1[4];
                    ldm4(p0, bBase[0] + qb + bSw[0][jb]);
                    ldm4(p1, bBase[1] + qb + bSw[1][jb]);
                    mma16816(D[0][0], (const uint32_t*)&af[0][kk], p0[0], p0[1]);
                    mma16816(D[0][1], (const uint32_t*)&af[0][kk], p0[2], p0[3]);
                    mma16816(D[0][2], (const uint32_t*)&af[0][kk], p1[0], p1[1]);
                    mma16816(D[0][3], (const uint32_t*)&af[0][kk], p1[2], p1[3]);
                    mma16816(D[1][0], (const uint32_t*)&af[1][kk], p0[0], p0[1]);
                    mma16816(D[1][1], (const uint32_t*)&af[1][kk], p0[2], p0[3]);
                    mma16816(D[1][2], (const uint32_t*)&af[1][kk], p1[0], p1[1]);
                    mma16816(D[1][3], (const uint32_t*)&af[1][kk], p1[2], p1[3]);
                }
            }

            // z store: warp's m32n32 K-half partial at [arow..][zcol..]
            {
                int g = lane >> 2, tq = lane & 3;
                #pragma unroll
                for (int mt = 0; mt < 2; mt++) {
                    int r0_ = arow + mt * 16 + g;
                    int cc = zcol + 2 * tq;
                    #pragma unroll
                    for (int nj = 0; nj < 4; nj++) {
                        *(float2*)(zst + r0_ * ZS2 + cc + nj * 8) =
                            make_float2(D[mt][nj][0], D[mt][nj][1]);
                        *(float2*)(zst + (r0_ + 8) * ZS2 + cc + nj * 8) =
                            make_float2(D[mt][nj][2], D[mt][nj][3]);
                    }
                }
            }
        }
        __syncthreads();

        {   // cell update
            #pragma unroll
            for (int cell = 0; cell < 2; cell++) {
                int du = du0 + 4 * cell;
                float zg4[4];
                #pragma unroll
                for (int g = 0; g < 4; g++) {
                    int lc = g * 8 + du;
                    zg4[g] = zst[b * ZS2 + lc] + zst[(64 + b) * ZS2 + lc]
                           + zst[b * ZS2 + 32 + lc] + zst[(64 + b) * ZS2 + 32 + lc]
                           + yv[cell * 4 + g];
                }
                float cn = fsigm(zg4[1]) * creg[cell] + fsigm(zg4[0]) * ftanh(zg4[2]);
                float hn = fsigm(zg4[3]) * ftanh(cn);
                creg[cell] = cn;
                if (t < TT - 1) {
                    __nv_bfloat16 hi = __float2bfloat16(hn);
                    __nv_bfloat16 lo = __float2bfloat16(hn - __bfloat162float(hi));
                    hstage[(0 * 64 + b) * 8 + du] = hi;
                    hstage[(1 * 64 + b) * 8 + du] = lo;
                } else {
                    g_hfin[dir][(size_t)(u0 + du) * BB + b] = hn;
                }
            }
        }

        if (t < TT - 1) {
            __syncthreads();
            // fragment-order h' write: thread (mtile, lane) packs 4 bf16 -> 8B STG
            {
                int mt8 = tid >> 5, ln = tid & 31;
                int r0 = mt8 * 16 + (ln >> 2);
                int c0 = (ln & 3) * 2;
                uint32_t v0 = *(const uint32_t*)&hstage[r0 * 8 + c0];        // a0/a2
                uint32_t v1 = *(const uint32_t*)&hstage[(r0 + 8) * 8 + c0];  // a1/a3
                char* dst = &g_hF[(t + 1) & 1][dir][0]
                          + (((size_t)(cta >> 1) * 8 + mt8) * 32 + ln) * 16
                          + (cta & 1) * 8;
                *(uint2*)dst = make_uint2(v0, v1);
            }
            __threadfence();
            __syncthreads();
            if (tid == 0) *(volatile unsigned*)&g_flag[dir][cta][0] = (unsigned)(t + 1);
        }
    }

    // final all-arrive barrier, then flag reset for graph replay
    __threadfence();
    __syncthreads();
    if (tid == 0) {
        volatile unsigned* gen = &g_gen[dir][0];
        unsigned g = *gen;
        unsigned a = atomicAdd(&g_cnt[dir][0], 1u);
        if (a == 63) {
            g_cnt[dir][0] = 0;
            __threadfence();
            *gen = g + 1;
        } else {
            while (*gen == g) {}
        }
        g_flag[dir][cta][0] = 0;
    }
}

// -------- head (reads fp32 g_hfin) --------
__global__ __launch_bounds__(256) void k_head(
    const float* __restrict__ W1, const float* __restrict__ b1,
    const float* __restrict__ W2, const float* __restrict__ b2,
    float* __restrict__ out)
{
    int b = blockIdx.x;
    int tid = threadIdx.x;
    int j = tid & 63, kq = tid >> 6;
    float s = 0.0f;
    for (int k = kq * 256; k < kq * 256 + 256; k++) {
        int dir = k >> 9, u = k & 511;
        float hv = g_hfin[dir][(size_t)u * BB + b];
        s += hv * W1[(size_t)k * 64 + j];
    }
    __shared__ float red[4][64];
    red[kq][j] = s;
    __syncthreads();
    if (tid < 64) {
        float sj = red[0][j] + red[1][j] + red[2][j] + red[3][j] + b1[j];
        red[0][j] = sj * W2[j];
    }
    __syncthreads();
    if (tid == 0) {
        float v = 0.0f;
        #pragma unroll
        for (int q = 0; q < 64; q++) v += red[0][q];
        out[b] = fsigm(v + b2[0]);
    }
}

extern "C" void kernel_launch(void* const* d_in, const int* in_sizes, int n_in,
                              void* d_out, int out_size)
{
    const int*   sent = (const int*)  d_in[0];
    const float* emb  = (const float*)d_in[1];
    const float* Wxf  = (const float*)d_in[2];
    const float* Whf  = (const float*)d_in[3];
    const float* bf   = (const float*)d_in[4];
    const float* Wxb  = (const float*)d_in[5];
    const float* Whb  = (const float*)d_in[6];
    const float* bbv  = (const float*)d_in[7];
    const float* W1   = (const float*)d_in[8];
    const float* b1   = (const float*)d_in[9];
    const float* W2   = (const float*)d_in[10];
    const float* b2   = (const float*)d_in[11];
    float* out = (float*)d_out;

    const int smem_rec = 32768 + 128 * ZS2 * 4 + 2048;   // 68608 B
    const int smem_xw  = 131072;
    cudaFuncSetAttribute(k_rec, cudaFuncAttributeMaxDynamicSharedMemorySize, smem_rec);
    cudaFuncSetAttribute(k_xw2, cudaFuncAttributeMaxDynamicSharedMemorySize, smem_xw);

    k_prepw<<<4096, 256>>>(Wxf, Wxb);
    k_prepx<<<dim3(512, 4), 256>>>(sent, emb);
    k_xw2<<<512 * 32, 256, smem_xw>>>(bf, bbv);
    k_rec<<<NCTA, NTHR, smem_rec>>>(Whf, Whb);
    k_head<<<64, 256>>>(W1, b1, W2, b2, out);
}

// round 17
// speedup vs baseline: 1.0172x; 1.0172x over previous
#include <cuda_runtime.h>
#include <cuda_bf16.h>
#include <math.h>
#include <stdint.h>

#define TT   512
#define BB   64
#define EE   256
#define UU   512
#define G4U  2048
#define NCTA 128   // 64 per direction
#define NTHR 256
#define ZS2  66    // k_rec z stride (floats, even)

// -------- device scratch --------
__device__ __align__(16) float g_Y[(size_t)2 * TT * G4U * BB];   // [dir][t][n][b]
// h as a pre-swizzled A-tile image: [parity][dir][131072 bytes]
// row = split*64 + b (128 rows x 1024 B); chunk c (16B) at row*1024 + ((c^(row&7))<<4)
__device__ __align__(128) char g_hA[2][2][131072];
__device__ __align__(16) __nv_bfloat16 g_X[TT][2][BB][EE];       // [t][split][b][e]
__device__ __align__(16) __nv_bfloat16 g_Wxb[2][G4U][EE];        // [dir][n][e]  (hi only)
__device__ unsigned g_flag[2][64][16];                           // 64B-spaced step flags
__device__ unsigned g_cnt[2][32];
__device__ unsigned g_gen[2][32];

// fast transcendentals (ex2.approx-based; saturate correctly at +-inf)
__device__ __forceinline__ float fsigm(float x) {
    return __fdividef(1.0f, 1.0f + __expf(-x));
}
__device__ __forceinline__ float ftanh(float x) {
    return __fdividef(2.0f, 1.0f + __expf(-2.0f * x)) - 1.0f;
}

__device__ __forceinline__ uint32_t smem_u32(const void* p) {
    uint32_t a;
    asm("{ .reg .u64 t; cvta.to.shared.u64 t, %1; cvt.u32.u64 %0, t; }" : "=r"(a) : "l"(p));
    return a;
}
__device__ __forceinline__ void ldm4(uint32_t* r, uint32_t addr) {
    asm volatile("ldmatrix.sync.aligned.m8n8.x4.shared.b16 {%0,%1,%2,%3}, [%4];"
                 : "=r"(r[0]), "=r"(r[1]), "=r"(r[2]), "=r"(r[3]) : "r"(addr));
}
__device__ __forceinline__ void mma16816(float* d, const uint32_t* a, uint32_t b0, uint32_t b1) {
    asm volatile("mma.sync.aligned.m16n8k16.row.col.f32.bf16.bf16.f32 "
                 "{%0,%1,%2,%3}, {%4,%5,%6,%7}, {%8,%9}, {%0,%1,%2,%3};"
                 : "+f"(d[0]), "+f"(d[1]), "+f"(d[2]), "+f"(d[3])
                 : "r"(a[0]), "r"(a[1]), "r"(a[2]), "r"(a[3]), "r"(b0), "r"(b1));
}
__device__ __forceinline__ unsigned ld_acq(const unsigned* p) {
    unsigned v;
    asm volatile("ld.acquire.gpu.u32 %0, [%1];" : "=r"(v) : "l"(p) : "memory");
    return v;
}
__device__ __forceinline__ void st_rel(unsigned* p, unsigned v) {
    asm volatile("st.release.gpu.u32 [%0], %1;" :: "l"(p), "r"(v) : "memory");
}
#define MBAR_INIT(a, c) \
    asm volatile("mbarrier.init.shared.b64 [%0], %1;" :: "r"(a), "r"((uint32_t)(c)) : "memory")
#define MBAR_EXPECT_TX(a, n) \
    asm volatile("mbarrier.arrive.expect_tx.shared.b64 _, [%0], %1;" :: "r"(a), "r"((uint32_t)(n)) : "memory")
#define MBAR_WAIT(a, ph) do {                                               \
    asm volatile("{ .reg .pred P1; WL%=:\n\t"                               \
        "mbarrier.try_wait.parity.acquire.cta.shared::cta.b64 P1, [%0], %1, 0x989680;\n\t" \
        "@P1 bra.uni WD%=;\n\t bra.uni WL%=;\n\t WD%=: }"                   \
        :: "r"(a), "r"((uint32_t)(ph)) : "memory");                         \
} while (0)
__device__ __forceinline__ void bulk_cp(uint32_t dst, const void* src, uint32_t bytes, uint32_t mbar) {
    asm volatile("cp.async.bulk.shared::cta.global.mbarrier::complete_tx::bytes [%0], [%1], %2, [%3];"
                 :: "r"(dst), "l"(src), "r"(bytes), "r"(mbar) : "memory");
}

// -------- prep: Wx -> bf16 hi, n-major --------
__global__ __launch_bounds__(256) void k_prepw(const float* __restrict__ Wxf,
                                               const float* __restrict__ Wxb)
{
    int bid = blockIdx.x;
    int dir = bid >> 11, n = bid & 2047;
    const float* Wx = dir ? Wxb : Wxf;
    int e = threadIdx.x;
    float w = Wx[(size_t)e * G4U + n];
    g_Wxb[dir][n][e] = __float2bfloat16(w);
}

// -------- prep: embedding gather -> bf16 hi/lo --------
__global__ __launch_bounds__(256) void k_prepx(const int* __restrict__ sent,
                                               const float* __restrict__ emb)
{
    int t = blockIdx.x;
    int b0 = blockIdx.y * 16;
    int tid = threadIdx.x;
    __shared__ int vrow[16];
    if (tid < 16) vrow[tid] = sent[(b0 + tid) * TT + t];
    __syncthreads();
    for (int j = 0; j < 16; j++) {
        int b = b0 + j;
        float v = emb[(size_t)vrow[j] * EE + tid];
        __nv_bfloat16 hi = __float2bfloat16(v);
        __nv_bfloat16 lo = __float2bfloat16(v - __bfloat162float(hi));
        g_X[t][0][b][tid] = hi;
        g_X[t][1][b][tid] = lo;
    }
}

// -------- input projection via HMMA: 2 timesteps per CTA (B loaded once) --------
__global__ __launch_bounds__(256) void k_xw2(const float* __restrict__ bf,
                                             const float* __restrict__ bbv)
{
    int bid = blockIdx.x;                // 256 tpair * 32
    int tpair = bid >> 5;
    int r5 = bid & 31;
    int dir = r5 >> 4, ntile = r5 & 15;

    extern __shared__ char sm[];
    char* smA = sm;                      // 64 KB
    char* smB = sm + 65536;              // 64 KB (persists across both t)
    float* zst = (float*)(sm + 131072);  // [128][129] = 66048 B (separate)

    int tid = threadIdx.x, lane = tid & 31, w = tid >> 5;
    uint32_t smA32 = smem_u32(smA), smB32 = smem_u32(smB);
    int arows = (w & 3) * 32;
    int brows = (w >> 2) * 64;

    // load B once
    {
        const uint4* Ws = (const uint4*)&g_Wxb[dir][0][0];
        #pragma unroll
        for (int idx = tid; idx < 4096; idx += 256) {
            int q = idx >> 5, c = idx & 31;
            uint4 v = __ldcg(Ws + ((size_t)(ntile * 128 + q)) * 32 + c);
            *(uint4*)(smB + q * 512 + ((c ^ (q & 7)) << 4)) = v;
        }
    }

    // fragment address precompute
    uint32_t aBase[2]; int ar7[2];
    uint32_t bBase[4]; int br7[4];
    int dA = (lane >> 4) & 1, dB = (lane >> 3) & 1;
    #pragma unroll
    for (int mi = 0; mi < 2; mi++) {
        int row = arows + mi * 16 + ((lane >> 3) & 1) * 8 + (lane & 7);
        aBase[mi] = smA32 + row * 512;
        ar7[mi] = row & 7;
    }
    #pragma unroll
    for (int nt = 0; nt < 4; nt++) {
        int row = brows + nt * 16 + ((lane >> 4) & 1) * 8 + (lane & 7);
        bBase[nt] = smB32 + row * 512;
        br7[nt] = row & 7;
    }

    for (int it = 0; it < 2; it++) {
        int t = tpair * 2 + it;

        // load A for this t
        {
            const uint4* Xs = (const uint4*)&g_X[t][0][0][0];
            #pragma unroll
            for (int idx = tid; idx < 4096; idx += 256) {
                int row = idx >> 5, c = idx & 31;
                uint4 v = __ldcg(Xs + idx);
                *(uint4*)(smA + row * 512 + ((c ^ (row & 7)) << 4)) = v;
            }
        }
        __syncthreads();

        float D[2][8][4];
        #pragma unroll
        for (int mi = 0; mi < 2; mi++)
            #pragma unroll
            for (int nj = 0; nj < 8; nj++)
                #pragma unroll
                for (int e = 0; e < 4; e++) D[mi][nj][e] = 0.0f;

        #pragma unroll 2
        for (int j = 0; j < 16; j++) {
            uint32_t af[2][4], bb[4][4];
            #pragma unroll
            for (int mi = 0; mi < 2; mi++)
                ldm4(af[mi], aBase[mi] + ((((2 * j + dA) ^ ar7[mi])) << 4));
            #pragma unroll
            for (int nt = 0; nt < 4; nt++)
                ldm4(bb[nt], bBase[nt] + ((((2 * j + dB) ^ br7[nt])) << 4));
            #pragma unroll
            for (int mi = 0; mi < 2; mi++)
                #pragma unroll
                for (int nt = 0; nt < 4; nt++) {
                    mma16816(D[mi][2 * nt + 0], af[mi], bb[nt][0], bb[nt][1]);
                    mma16816(D[mi][2 * nt + 1], af[mi], bb[nt][2], bb[nt][3]);
                }
        }

        // stage D into zst
        {
            int g = lane >> 2, tq = lane & 3;
            #pragma unroll
            for (int mi = 0; mi < 2; mi++)
                #pragma unroll
                for (int nj = 0; nj < 8; nj++) {
                    int r = arows + mi * 16 + g;
                    int c = brows + nj * 8 + 2 * tq;
                    zst[r * 129 + c]           = D[mi][nj][0];
                    zst[r * 129 + c + 1]       = D[mi][nj][1];
                    zst[(r + 8) * 129 + c]     = D[mi][nj][2];
                    zst[(r + 8) * 129 + c + 1] = D[mi][nj][3];
                }
        }
        __syncthreads();

        // reduce b-split, add bias, transpose-write Y[n][b]
        {
            const float* bias = dir ? bbv : bf;
            float* Y = g_Y + ((size_t)dir * TT + t) * (size_t)(G4U * BB)
                           + (size_t)ntile * 128 * BB;
            #pragma unroll
            for (int rep = 0; rep < 8; rep++) {
                int task = tid + 256 * rep;
                int n = task >> 4, b4 = (task & 15) << 2;
                float bn = bias[ntile * 128 + n];
                float4 o;
                o.x = zst[(b4 + 0) * 129 + n] + zst[(b4 + 64) * 129 + n] + bn;
                o.y = zst[(b4 + 1) * 129 + n] + zst[(b4 + 65) * 129 + n] + bn;
                o.z = zst[(b4 + 2) * 129 + n] + zst[(b4 + 66) * 129 + n] + bn;
                o.w = zst[(b4 + 3) * 129 + n] + zst[(b4 + 67) * 129 + n] + bn;
                *(float4*)(Y + (size_t)n * BB + b4) = o;
            }
        }
        __syncthreads();   // zst reads done before next-t A overwrite / zst rewrite
    }
}

// -------- persistent HMMA recurrence: bulk-copy A image, slim sync path --------
__global__ __launch_bounds__(NTHR, 1) void k_rec(
    const float* __restrict__ Whf, const float* __restrict__ Whb)
{
    extern __shared__ char dsm[];
    char* smA  = dsm;                        // 131072 B (A image, same layout as g_hA)
    char* smB  = dsm + 131072;               // 32768 B (W_hi)
    float* zst = (float*)(dsm + 131072 + 32768);   // [128][ZS2]
    __nv_bfloat16* hstage = (__nv_bfloat16*)smA;
    __shared__ __align__(8) unsigned long long s_mbar[4];

    int tid = threadIdx.x, lane = tid & 31, w = tid >> 5;
    int dir = blockIdx.x >> 6;
    int cta = blockIdx.x & 63;
    int u0  = cta * 8;
    const float* Wh = dir ? Whb : Whf;

    uint32_t mbar0 = smem_u32(&s_mbar[0]);
    if (tid < 4) MBAR_INIT(mbar0 + tid * 8, 1);

    // B build (once): 32 rows of W_hi
    for (int idx = tid; idx < 32 * 512; idx += NTHR) {
        int n = idx >> 9, k = idx & 511;
        float wv = Wh[(size_t)k * G4U + ((n >> 3) * UU + u0 + (n & 7))];
        __nv_bfloat16 hi = __float2bfloat16(wv);
        uint32_t off = (uint32_t)(n * 1024 + ((((k >> 3) ^ (n & 7))) << 4) + (k & 7) * 2);
        *(__nv_bfloat16*)(smB + off) = hi;
    }
    for (int i = tid; i < 128 * ZS2; i += NTHR) zst[i] = 0.0f;

    // warp tiling: m-block = w&3 (rows (w&3)*32..+32), K-half = w>>2
    uint32_t smA32 = smem_u32(smA), smB32 = smem_u32(smB);
    int arow = (w & 3) * 32;
    int kh   = w >> 2;
    int zcol = kh * 32;
    int qlo  = kh * 4;
    uint32_t mymbar = mbar0 + (w & 3) * 8;

    uint32_t aBase[2], bBase[2], aSw[2][4], bSw[2][4];
    {
        int dA = (lane >> 4) & 1;
        #pragma unroll
        for (int mt = 0; mt < 2; mt++) {
            int row = arow + mt * 16 + ((lane >> 3) & 1) * 8 + (lane & 7);
            aBase[mt] = smA32 + row * 1024;
            #pragma unroll
            for (int j = 0; j < 4; j++)
                aSw[mt][j] = (uint32_t)(((2 * j + dA) ^ (row & 7)) << 4);
        }
        int dB = (lane >> 3) & 1;
        #pragma unroll
        for (int nt = 0; nt < 2; nt++) {
            int row = nt * 16 + ((lane >> 4) & 1) * 8 + (lane & 7);
            bBase[nt] = smB32 + row * 1024;
            #pragma unroll
            for (int j = 0; j < 4; j++)
                bSw[nt][j] = (uint32_t)(((2 * j + dB) ^ (row & 7)) << 4);
        }
    }

    int b = tid & 63, du0 = tid >> 6;
    float creg[2] = {0.0f, 0.0f};
    const float* Ybase = g_Y + (size_t)dir * TT * (size_t)(G4U * BB);
    int ph = 0;
    __syncthreads();

    for (int t = 0; t < TT; t++) {
        int ttv = dir ? (TT - 1 - t) : t;
        const float* Yt = Ybase + (size_t)ttv * (size_t)(G4U * BB);
        float yv[8];
        #pragma unroll
        for (int g = 0; g < 4; g++) {
            yv[g]     = __ldcg(Yt + (size_t)(g * UU + u0 + du0) * BB + b);
            yv[4 + g] = __ldcg(Yt + (size_t)(g * UU + u0 + du0 + 4) * BB + b);
        }

        if (t > 0) {
            // only warps 0-1 poll producers; warps 2-7 park on their mbarrier
            if (tid < 64) {
                while (ld_acq((const unsigned*)&g_flag[dir][tid][0]) < (unsigned)t) {}
                asm volatile("bar.sync 1, 64;" ::: "memory");
            }
            if (tid < 4) {
                const char* src = &g_hA[t & 1][dir][0] + tid * 32768;
                MBAR_EXPECT_TX(mbar0 + tid * 8, 32768);
                bulk_cp(smA32 + tid * 32768, src, 32768, mbar0 + tid * 8);
            }
            MBAR_WAIT(mymbar, ph);

            float D[2][4][4];
            #pragma unroll
            for (int mt = 0; mt < 2; mt++)
                #pragma unroll
                for (int nj = 0; nj < 4; nj++)
                    #pragma unroll
                    for (int e = 0; e < 4; e++) D[mt][nj][e] = 0.0f;

            for (int q = qlo; q < qlo + 4; q++) {
                uint32_t qo = (uint32_t)(q * 128);
                #pragma unroll
                for (int j = 0; j < 4; j++) {
                    uint32_t a0[4], a1[4], p0[4], p1[4];
                    ldm4(a0, aBase[0] + qo + aSw[0][j]);
                    ldm4(a1, aBase[1] + qo + aSw[1][j]);
                    ldm4(p0, bBase[0] + qo + bSw[0][j]);
                    ldm4(p1, bBase[1] + qo + bSw[1][j]);
                    mma16816(D[0][0], a0, p0[0], p0[1]);
                    mma16816(D[0][1], a0, p0[2], p0[3]);
                    mma16816(D[0][2], a0, p1[0], p1[1]);
                    mma16816(D[0][3], a0, p1[2], p1[3]);
                    mma16816(D[1][0], a1, p0[0], p0[1]);
                    mma16816(D[1][1], a1, p0[2], p0[3]);
                    mma16816(D[1][2], a1, p1[0], p1[1]);
                    mma16816(D[1][3], a1, p1[2], p1[3]);
                }
            }
            ph ^= 1;

            // z store: warp's m32n32 K-half partial at [arow..][zcol..]
            {
                int g = lane >> 2, tq = lane & 3;
                #pragma unroll
                for (int mt = 0; mt < 2; mt++) {
                    int r0_ = arow + mt * 16 + g;
                    int cc = zcol + 2 * tq;
                    #pragma unroll
                    for (int nj = 0; nj < 4; nj++) {
                        *(float2*)(zst + r0_ * ZS2 + cc + nj * 8) =
                            make_float2(D[mt][nj][0], D[mt][nj][1]);
                        *(float2*)(zst + (r0_ + 8) * ZS2 + cc + nj * 8) =
                            make_float2(D[mt][nj][2], D[mt][nj][3]);
                    }
                }
            }
        }
        __syncthreads();

        {   // cell update: z = (hi@b + lo@64+b) over both K-half planes + Y
            #pragma unroll
            for (int cell = 0; cell < 2; cell++) {
                int du = du0 + 4 * cell;
                float zg4[4];
                #pragma unroll
                for (int g = 0; g < 4; g++) {
                    int lc = g * 8 + du;
                    zg4[g] = zst[b * ZS2 + lc] + zst[(64 + b) * ZS2 + lc]
                           + zst[b * ZS2 + 32 + lc] + zst[(64 + b) * ZS2 + 32 + lc]
                           + yv[cell * 4 + g];
                }
                float cn = fsigm(zg4[1]) * creg[cell] + fsigm(zg4[0]) * ftanh(zg4[2]);
                float hn = fsigm(zg4[3]) * ftanh(cn);
                creg[cell] = cn;
                __nv_bfloat16 hi = __float2bfloat16(hn);
                __nv_bfloat16 lo = __float2bfloat16(hn - __bfloat162float(hi));
                hstage[(0 * 64 + b) * 8 + du] = hi;
                hstage[(1 * 64 + b) * 8 + du] = lo;
            }
        }
        __syncthreads();

        // h' write into the pre-swizzled A image: row = sp*64+b, chunk = cta
        if (tid < 128) {
            int sp = tid >> 6, br = tid & 63;
            int row = sp * 64 + br;
            uint4 v = *(const uint4*)(hstage + (sp * 64 + br) * 8);
            char* dst = &g_hA[(t + 1) & 1][dir][0]
                      + row * 1024 + ((cta ^ (row & 7)) << 4);
            *(uint4*)dst = v;
        }

        if (t < TT - 1) {
            __syncthreads();
            if (tid == 0) st_rel(&g_flag[dir][cta][0], (unsigned)(t + 1));
        }
    }

    // final all-arrive barrier, then flag reset for graph replay
    __threadfence();
    __syncthreads();
    if (tid == 0) {
        volatile unsigned* gen = &g_gen[dir][0];
        unsigned g = *gen;
        unsigned a = atomicAdd(&g_cnt[dir][0], 1u);
        if (a == 63) {
            g_cnt[dir][0] = 0;
            __threadfence();
            *gen = g + 1;
        } else {
            while (*gen == g) {}
        }
        g_flag[dir][cta][0] = 0;
    }
}

// -------- head (reads the parity-0 A image) --------
__global__ __launch_bounds__(256) void k_head(
    const float* __restrict__ W1, const float* __restrict__ b1,
    const float* __restrict__ W2, const float* __restrict__ b2,
    float* __restrict__ out)
{
    int b = blockIdx.x;
    int tid = threadIdx.x;
    int j = tid & 63, kq = tid >> 6;
    float s = 0.0f;
    for (int k = kq * 256; k < kq * 256 + 256; k++) {
        int dir = k >> 9, u = k & 511;
        const char* img = &g_hA[0][dir][0];
        int rh = b, rl = 64 + b;
        float hv =
            __bfloat162float(*(const __nv_bfloat16*)(img + rh * 1024 + ((((u >> 3) ^ (rh & 7))) << 4) + (u & 7) * 2)) +
            __bfloat162float(*(const __nv_bfloat16*)(img + rl * 1024 + ((((u >> 3) ^ (rl & 7))) << 4) + (u & 7) * 2));
        s += hv * W1[(size_t)k * 64 + j];
    }
    __shared__ float red[4][64];
    red[kq][j] = s;
    __syncthreads();
    if (tid < 64) {
        float sj = red[0][j] + red[1][j] + red[2][j] + red[3][j] + b1[j];
        red[0][j] = sj * W2[j];
    }
    __syncthreads();
    if (tid == 0) {
        float v = 0.0f;
        #pragma unroll
        for (int q = 0; q < 64; q++) v += red[0][q];
        out[b] = fsigm(v + b2[0]);
    }
}

extern "C" void kernel_launch(void* const* d_in, const int* in_sizes, int n_in,
                              void* d_out, int out_size)
{
    const int*   sent = (const int*)  d_in[0];
    const float* emb  = (const float*)d_in[1];
    const float* Wxf  = (const float*)d_in[2];
    const float* Whf  = (const float*)d_in[3];
    const float* bf   = (const float*)d_in[4];
    const float* Wxb  = (const float*)d_in[5];
    const float* Whb  = (const float*)d_in[6];
    const float* bbv  = (const float*)d_in[7];
    const float* W1   = (const float*)d_in[8];
    const float* b1   = (const float*)d_in[9];
    const float* W2   = (const float*)d_in[10];
    const float* b2   = (const float*)d_in[11];
    float* out = (float*)d_out;

    const int smem_rec = 131072 + 32768 + 128 * ZS2 * 4;   // 197632 B
    const int smem_xw  = 65536 + 65536 + 128 * 129 * 4;    // 197120 B
    cudaFuncSetAttribute(k_rec, cudaFuncAttributeMaxDynamicSharedMemorySize, smem_rec);
    cudaFuncSetAttribute(k_xw2, cudaFuncAttributeMaxDynamicSharedMemorySize, smem_xw);

    k_prepw<<<4096, 256>>>(Wxf, Wxb);
    k_prepx<<<dim3(512, 4), 256>>>(sent, emb);
    k_xw2<<<256 * 32, 256, smem_xw>>>(bf, bbv);
    k_rec<<<NCTA, NTHR, smem_rec>>>(Whf, Whb);
    k_head<<<64, 256>>>(W1, b1, W2, b2, out);
}